// round 1
// baseline (speedup 1.0000x reference)
#include <cuda_runtime.h>
#include <math.h>

#define NSEQ 10000
#define LSEQ 32
#define DIM  256
#define GDIM 1024            // 4*D
#define NTOK (NSEQ * LSEQ)   // 320000

#define P2_GRID    148
#define P2_THREADS 288       // 9 warps: 32 j-lanes x 9 row-groups of 8 rows
#define ROWS_MAX   72
#define P2_SMEM    (3 * ROWS_MAX * DIM * 4)   // h0, h1, c (fp32) = 221184 B

// ---------------- device scratch (no runtime allocation allowed) ----------------
__device__ float g_xproj[(size_t)NTOK * GDIM];  // [token m = n*32+t][4D] fp32
__device__ float g_WihT[DIM * GDIM];            // [k][g] transposed
__device__ float g_WhhT[DIM * GDIM];            // [k][g] transposed
__device__ float g_bias[GDIM];                  // b_ih + b_hh

// ---------------- helpers ----------------
__device__ __forceinline__ float sigf(float x) {
    return 1.0f / (1.0f + __expf(-x));
}
__device__ __forceinline__ float tanhfast(float x) {
    // tanh(x) = 2/(1+e^{-2x}) - 1 ; saturates correctly for |x| large
    return 2.0f / (1.0f + __expf(-2.0f * x)) - 1.0f;
}

// ---------------- prep: transpose weights, fold biases ----------------
__global__ void prep_kernel(const float* __restrict__ W_ih,
                            const float* __restrict__ W_hh,
                            const float* __restrict__ b_ih,
                            const float* __restrict__ b_hh) {
    int idx = blockIdx.x * blockDim.x + threadIdx.x;
    int total = DIM * GDIM;
    for (int i = idx; i < total; i += gridDim.x * blockDim.x) {
        int k = i / GDIM;
        int g = i % GDIM;
        g_WihT[i] = W_ih[g * DIM + k];
        g_WhhT[i] = W_hh[g * DIM + k];
    }
    if (idx < GDIM) g_bias[idx] = b_ih[idx] + b_hh[idx];
}

// ---------------- phase 1: x_proj = X @ W_ih^T + (b_ih + b_hh) ----------------
// X flat: [NTOK][256] (token m = n*L + t). Tiles: 128x128x16, 256 thr, 8x8/thread.
__global__ __launch_bounds__(256, 2)
void xproj_gemm_kernel(const float* __restrict__ X) {
    __shared__ float As[16][132];   // [k][m] transposed, padded
    __shared__ float Bs[16][128];   // [k][g]

    const int tid  = threadIdx.x;
    const int m0   = blockIdx.y * 128;
    const int g0   = blockIdx.x * 128;
    const int tcol = tid & 15;
    const int trow = tid >> 4;

    float acc[8][8];
#pragma unroll
    for (int i = 0; i < 8; i++)
#pragma unroll
        for (int j = 0; j < 8; j++) acc[i][j] = 0.0f;

    for (int k0 = 0; k0 < DIM; k0 += 16) {
        // load A tile 128x16 (transposed into As)
#pragma unroll
        for (int l = 0; l < 2; l++) {
            int f  = tid + l * 256;
            int r  = f >> 2;
            int c4 = (f & 3) << 2;
            float4 v = *(const float4*)(X + (size_t)(m0 + r) * DIM + k0 + c4);
            As[c4 + 0][r] = v.x;
            As[c4 + 1][r] = v.y;
            As[c4 + 2][r] = v.z;
            As[c4 + 3][r] = v.w;
        }
        // load B tile 16x128 (already [k][g] layout -> coalesced)
#pragma unroll
        for (int l = 0; l < 2; l++) {
            int f  = tid + l * 256;
            int r  = f >> 5;
            int c4 = (f & 31) << 2;
            *(float4*)&Bs[r][c4] =
                *(const float4*)(g_WihT + (size_t)(k0 + r) * GDIM + g0 + c4);
        }
        __syncthreads();
#pragma unroll
        for (int k = 0; k < 16; k++) {
            float a[8], b[8];
            *(float4*)&a[0] = *(const float4*)&As[k][trow * 8];
            *(float4*)&a[4] = *(const float4*)&As[k][trow * 8 + 4];
            *(float4*)&b[0] = *(const float4*)&Bs[k][tcol * 8];
            *(float4*)&b[4] = *(const float4*)&Bs[k][tcol * 8 + 4];
#pragma unroll
            for (int i = 0; i < 8; i++)
#pragma unroll
                for (int j = 0; j < 8; j++)
                    acc[i][j] = fmaf(a[i], b[j], acc[i][j]);
        }
        __syncthreads();
    }

    // epilogue: add folded bias, write fp32 x_proj[m][g]
    const float* bp = g_bias + g0 + tcol * 8;
    float b0 = bp[0], b1 = bp[1], b2 = bp[2], b3 = bp[3];
    float b4 = bp[4], b5 = bp[5], b6 = bp[6], b7 = bp[7];
#pragma unroll
    for (int i = 0; i < 8; i++) {
        int m = m0 + trow * 8 + i;
        float* dst = g_xproj + (size_t)m * GDIM + g0 + tcol * 8;
        float4 v0, v1;
        v0.x = acc[i][0] + b0; v0.y = acc[i][1] + b1;
        v0.z = acc[i][2] + b2; v0.w = acc[i][3] + b3;
        v1.x = acc[i][4] + b4; v1.y = acc[i][5] + b5;
        v1.z = acc[i][6] + b6; v1.w = acc[i][7] + b7;
        *(float4*)(dst)     = v0;
        *(float4*)(dst + 4) = v1;
    }
}

// ---------------- phase 2: recurrence ----------------
// grid = 148 (one wave), each CTA owns rows [n0, n1) (<= 68 rows), runs all 32 steps.
// h double-buffered in smem (race-free vs gate-column chunks); c in smem.
__global__ __launch_bounds__(P2_THREADS, 1)
void lstm_rec_kernel(const int* __restrict__ lengths, float* __restrict__ out) {
    extern __shared__ float smem[];
    float* h0  = smem;                        // [ROWS_MAX][DIM]
    float* h1  = smem + ROWS_MAX * DIM;       // [ROWS_MAX][DIM]
    float* cst = smem + 2 * ROWS_MAX * DIM;   // [ROWS_MAX][DIM]
    __shared__ int slen[ROWS_MAX];

    const int bid  = blockIdx.x;
    const int n0   = (bid * NSEQ) / P2_GRID;
    const int n1   = ((bid + 1) * NSEQ) / P2_GRID;
    const int rows = n1 - n0;
    const int tid  = threadIdx.x;
    const int jl   = tid & 31;   // hidden lane within 32-col chunk
    const int rg   = tid >> 5;   // row group (0..8), 8 rows each

    for (int i = tid; i < 3 * ROWS_MAX * DIM; i += P2_THREADS) smem[i] = 0.0f;
    for (int i = tid; i < ROWS_MAX; i += P2_THREADS)
        slen[i] = (i < rows) ? lengths[n0 + i] : 0;
    __syncthreads();

    for (int t = 0; t < LSEQ; t++) {
        const float* hc = (t & 1) ? h1 : h0;   // read h_t
        float*       hn = (t & 1) ? h0 : h1;   // write h_{t+1}

        for (int jc = 0; jc < 8; jc++) {
            const int j = (jc << 5) + jl;      // hidden index 0..255

            float acc0[8], acc1[8], acc2[8], acc3[8];
            // init accumulators from x_proj (biases already folded in)
#pragma unroll
            for (int rr = 0; rr < 8; rr++) {
                int r = (rg << 3) + rr;
                if (r < rows) {
                    const float* xp =
                        g_xproj + ((size_t)(n0 + r) * LSEQ + t) * GDIM + j;
                    acc0[rr] = xp[0];
                    acc1[rr] = xp[256];
                    acc2[rr] = xp[512];
                    acc3[rr] = xp[768];
                } else {
                    acc0[rr] = acc1[rr] = acc2[rr] = acc3[rr] = 0.0f;
                }
            }

            const float* wp = g_WhhT + j;
            for (int k = 0; k < DIM; k += 4) {
                float4 av[8];
#pragma unroll
                for (int rr = 0; rr < 8; rr++)
                    av[rr] = *(const float4*)&hc[(((rg << 3) + rr) * DIM) + k];
#pragma unroll
                for (int kk = 0; kk < 4; kk++) {
                    const float* w = wp + (size_t)(k + kk) * GDIM;
                    float w0 = w[0], w1 = w[256], w2 = w[512], w3 = w[768];
#pragma unroll
                    for (int rr = 0; rr < 8; rr++) {
                        float a = (kk == 0) ? av[rr].x
                                : (kk == 1) ? av[rr].y
                                : (kk == 2) ? av[rr].z
                                            : av[rr].w;
                        acc0[rr] = fmaf(a, w0, acc0[rr]);
                        acc1[rr] = fmaf(a, w1, acc1[rr]);
                        acc2[rr] = fmaf(a, w2, acc2[rr]);
                        acc3[rr] = fmaf(a, w3, acc3[rr]);
                    }
                }
            }

            // epilogue: gate math + masked state update (PyTorch gate order i,f,g,o)
#pragma unroll
            for (int rr = 0; rr < 8; rr++) {
                int r = (rg << 3) + rr;
                if (r < rows) {
                    float ig = sigf(acc0[rr]);
                    float fg = sigf(acc1[rr]);
                    float gg = tanhfast(acc2[rr]);
                    float og = sigf(acc3[rr]);
                    float cold = cst[r * DIM + j];
                    float cn   = fmaf(fg, cold, ig * gg);
                    float hv   = og * tanhfast(cn);
                    if (t < slen[r]) {
                        cst[r * DIM + j] = cn;
                        hn[r * DIM + j]  = hv;
                    } else {
                        hn[r * DIM + j] = hc[r * DIM + j];
                    }
                }
            }
        }
        __syncthreads();   // h_{t+1} fully written before next step reads it
    }

    // after t=31 (odd), final h lives in h0
    for (int i = tid; i < rows * DIM; i += P2_THREADS)
        out[(size_t)n0 * DIM + i] = h0[i];
}

// ---------------- launch ----------------
extern "C" void kernel_launch(void* const* d_in, const int* in_sizes, int n_in,
                              void* d_out, int out_size) {
    const float* x       = (const float*)d_in[0];
    const int*   lengths = (const int*)d_in[1];
    const float* W_ih    = (const float*)d_in[2];
    const float* W_hh    = (const float*)d_in[3];
    const float* b_ih    = (const float*)d_in[4];
    const float* b_hh    = (const float*)d_in[5];
    float*       out     = (float*)d_out;
    (void)in_sizes; (void)n_in; (void)out_size;

    prep_kernel<<<512, 256>>>(W_ih, W_hh, b_ih, b_hh);

    dim3 g1(GDIM / 128, NTOK / 128);   // (8, 2500)
    xproj_gemm_kernel<<<g1, 256>>>(x);

    // opt-in to >48KB dynamic smem; attribute persists, ignore error (e.g. during capture)
    (void)cudaFuncSetAttribute(lstm_rec_kernel,
                               cudaFuncAttributeMaxDynamicSharedMemorySize, P2_SMEM);
    lstm_rec_kernel<<<P2_GRID, P2_THREADS, P2_SMEM>>>(lengths, out);
}

// round 3
// speedup vs baseline: 5.2963x; 5.2963x over previous
#include <cuda_runtime.h>
#include <math.h>
#include <stdint.h>

#define NSEQ 10000
#define LSEQ 32
#define DIM  256
#define GDIM 1024
#define KDIM 512
#define GRID 148
#define NTHR 256
#define RP   80          // padded rows per CTA (5 x m16 tiles)
#define PSTRIDE 520      // A-panel row stride in floats (bank-conflict-free)

// ---------------- device scratch (no runtime allocation allowed) ----------------
__device__ float g_Wfrag[524288];        // fused [W_ih;W_hh] in exact B-fragment order, tf32-rounded
__device__ float g_bias[GDIM];           // b_ih + b_hh, original (gate,j) order
__device__ float g_hfrag[GRID * 20480];  // per-CTA h state, fragment order (float4/thread)
__device__ float g_cfrag[GRID * 20480];  // per-CTA c state, fragment order

// ---------------- helpers ----------------
__device__ __forceinline__ float sigf(float x) {
    return __fdividef(1.0f, 1.0f + __expf(-x));
}
__device__ __forceinline__ float tanhf_(float x) {
    return fmaf(2.0f, __fdividef(1.0f, 1.0f + __expf(-2.0f * x)), -1.0f);
}
__device__ __forceinline__ float tf32r(float x) {
    uint32_t u; asm("cvt.rna.tf32.f32 %0, %1;" : "=r"(u) : "f"(x));
    return __uint_as_float(u);
}
__device__ __forceinline__ void mma_tf32(float c[4],
                                         uint32_t a0, uint32_t a1, uint32_t a2, uint32_t a3,
                                         uint32_t b0, uint32_t b1) {
    asm volatile(
        "mma.sync.aligned.m16n8k8.row.col.f32.tf32.tf32.f32 "
        "{%0,%1,%2,%3},{%4,%5,%6,%7},{%8,%9},{%0,%1,%2,%3};"
        : "+f"(c[0]), "+f"(c[1]), "+f"(c[2]), "+f"(c[3])
        : "r"(a0), "r"(a1), "r"(a2), "r"(a3), "r"(b0), "r"(b1));
}

// ---------------- prep: build fragment-ordered fused weights + folded bias ----------------
// Gate-column permutation (position p in [0,1024)):
//   nt=p>>8, p8=p&255, w=p8>>5, c32=p8&31, s=c32>>3, c8=c32&7
//   unit u = (s>>1)*4 + (c8>>1); gate = (s&1)*2 + (c8&1)   (0=i,1=f,2=g,3=o)
//   hidden j = nt*64 + w*8 + u;  original W row = gate*256 + j
// B-fragment storage: g_Wfrag[((s8*64+ks)*32+lane)*2 + r] = Wfused[n=s8*8+(lane>>2)][k=ks*8+(lane&3)+4r]
__global__ void prep_kernel(const float* __restrict__ W_ih, const float* __restrict__ W_hh,
                            const float* __restrict__ b_ih, const float* __restrict__ b_hh) {
    int idx0 = blockIdx.x * blockDim.x + threadIdx.x;
    for (int idx = idx0; idx < 524288; idx += gridDim.x * blockDim.x) {
        int r    = idx & 1;
        int lane = (idx >> 1) & 31;
        int ks   = (idx >> 6) & 63;
        int s8   = idx >> 12;
        int n    = s8 * 8 + (lane >> 2);
        int k    = ks * 8 + (lane & 3) + 4 * r;
        int nt = n >> 8, p8 = n & 255;
        int w = p8 >> 5, c32 = p8 & 31, s = c32 >> 3, c8 = c32 & 7;
        int u    = ((s >> 1) << 2) + (c8 >> 1);
        int gate = ((s & 1) << 1) + (c8 & 1);
        int j    = nt * 64 + w * 8 + u;
        int row  = gate * 256 + j;
        float v  = (k < 256) ? W_ih[row * 256 + k] : W_hh[row * 256 + (k - 256)];
        g_Wfrag[idx] = tf32r(v);
    }
    if (idx0 < GDIM) g_bias[idx0] = b_ih[idx0] + b_hh[idx0];
}

// ---------------- fused persistent LSTM (tf32 tensor cores) ----------------
__global__ __launch_bounds__(NTHR, 1)
void lstm_fused_kernel(const float* __restrict__ x, const int* __restrict__ lengths,
                       float* __restrict__ out) {
    extern __shared__ float panel[];   // [RP][PSTRIDE]: cols 0..255 = x_t, 256..511 = h_t
    __shared__ float sbias[GDIM];
    __shared__ int   slen[RP];

    const int bid = blockIdx.x;
    const int n0  = (bid * NSEQ) / GRID;
    const int n1  = ((bid + 1) * NSEQ) / GRID;
    const int R   = n1 - n0;           // 67 or 68
    const int tid = threadIdx.x;
    const int w   = tid >> 5, lane = tid & 31, g = lane >> 2, tig = lane & 3;

    float*  hfr  = g_hfrag + bid * 20480;
    float*  cfr  = g_cfrag + bid * 20480;
    float4* hfr4 = (float4*)hfr;
    float4* cfr4 = (float4*)cfr;

    for (int i = tid; i < GDIM; i += NTHR) sbias[i] = g_bias[i];
    for (int i = tid; i < RP; i += NTHR)   slen[i] = (i < R) ? lengths[n0 + i] : 0;
    for (int i = tid; i < RP * PSTRIDE; i += NTHR) panel[i] = 0.0f;
    for (int i = tid; i < 20480; i += NTHR) { hfr[i] = 0.0f; cfr[i] = 0.0f; }
    __syncthreads();

    for (int t = 0; t < LSEQ; t++) {
        // ---- stage x_t (rows < R; pad rows stay zero) ----
        const float4* xg = (const float4*)(x + (size_t)n0 * LSEQ * DIM + (size_t)t * DIM);
        for (int i = tid; i < R * 64; i += NTHR) {
            int r = i >> 6, c = i & 63;
            float4 v = xg[(size_t)r * 2048 + c];   // row stride = LSEQ*DIM/4
            *(float4*)&panel[r * PSTRIDE + c * 4] = v;
        }
        // ---- stage h_t from fragment-ordered scratch ----
        for (int f = tid; f < 5120; f += NTHR) {
            float4 hv = hfr4[f];
            int nt = f / 1280, rem = f - nt * 1280;
            int m = rem >> 8, rem2 = rem & 255;
            int w2 = rem2 >> 5, lane2 = rem2 & 31;
            int g2 = lane2 >> 2, tg2 = lane2 & 3;
            int j0 = nt * 64 + w2 * 8 + tg2;
            int r0 = m * 16 + g2;
            panel[r0 * PSTRIDE + 256 + j0]           = hv.x;
            panel[(r0 + 8) * PSTRIDE + 256 + j0]     = hv.y;
            panel[r0 * PSTRIDE + 256 + j0 + 4]       = hv.z;
            panel[(r0 + 8) * PSTRIDE + 256 + j0 + 4] = hv.w;
        }
        __syncthreads();

        for (int nt = 0; nt < 4; nt++) {
            const int j = nt * 64 + w * 8 + tig;
            const float bi0 = sbias[j],       bf0 = sbias[256 + j];
            const float bg0 = sbias[512 + j], bo0 = sbias[768 + j];
            const float bi1 = sbias[j + 4],       bf1 = sbias[256 + j + 4];
            const float bg1 = sbias[512 + j + 4], bo1 = sbias[768 + j + 4];

            float C[5][4][4];
#pragma unroll
            for (int m = 0; m < 5; m++)
#pragma unroll
                for (int s = 0; s < 4; s++)
#pragma unroll
                    for (int q = 0; q < 4; q++) C[m][s][q] = 0.0f;

            const float2* bp[4];
#pragma unroll
            for (int s = 0; s < 4; s++) {
                int s8 = nt * 32 + w * 4 + s;
                bp[s] = (const float2*)g_Wfrag + (size_t)s8 * 2048 + lane;
            }
            float2 Bc[4];
#pragma unroll
            for (int s = 0; s < 4; s++) Bc[s] = bp[s][0];

            int rowb[5];
#pragma unroll
            for (int m = 0; m < 5; m++) rowb[m] = (m * 16 + g) * PSTRIDE;

#pragma unroll 2
            for (int ks = 0; ks < 64; ks++) {
                float2 Bn[4];
                int ks2 = (ks < 63) ? ks + 1 : 63;
#pragma unroll
                for (int s = 0; s < 4; s++) Bn[s] = bp[s][ks2 * 32];
                const int k = ks * 8 + tig;
#pragma unroll
                for (int m = 0; m < 5; m++) {
                    const float* ap = panel + rowb[m] + k;
                    uint32_t a0 = __float_as_uint(ap[0]);
                    uint32_t a2 = __float_as_uint(ap[4]);
                    uint32_t a1 = __float_as_uint(ap[8 * PSTRIDE]);
                    uint32_t a3 = __float_as_uint(ap[8 * PSTRIDE + 4]);
#pragma unroll
                    for (int s = 0; s < 4; s++)
                        mma_tf32(C[m][s], a0, a1, a2, a3,
                                 __float_as_uint(Bc[s].x), __float_as_uint(Bc[s].y));
                }
#pragma unroll
                for (int s = 0; s < 4; s++) Bc[s] = Bn[s];
            }

            // ---- register-local epilogue: thread holds i,f,g,o of its units ----
#pragma unroll
            for (int m = 0; m < 5; m++) {
                int f4 = ((nt * 5 + m) * 8 + w) * 32 + lane;
                float4 cold = cfr4[f4];
                float4 hold = hfr4[f4];
                int r0 = m * 16 + g, r1 = r0 + 8;
                bool v0 = t < slen[r0], v1 = t < slen[r1];
                float4 cn, hn;
                {   // q0: unit tig, row r0
                    float ii = sigf(C[m][0][0] + bi0), ff = sigf(C[m][0][1] + bf0);
                    float gg = tanhf_(C[m][1][0] + bg0), oo = sigf(C[m][1][1] + bo0);
                    float c2 = fmaf(ff, cold.x, ii * gg);
                    float h2 = oo * tanhf_(c2);
                    cn.x = v0 ? c2 : cold.x;  hn.x = v0 ? h2 : hold.x;
                }
                {   // q1: unit tig, row r1
                    float ii = sigf(C[m][0][2] + bi0), ff = sigf(C[m][0][3] + bf0);
                    float gg = tanhf_(C[m][1][2] + bg0), oo = sigf(C[m][1][3] + bo0);
                    float c2 = fmaf(ff, cold.y, ii * gg);
                    float h2 = oo * tanhf_(c2);
                    cn.y = v1 ? c2 : cold.y;  hn.y = v1 ? h2 : hold.y;
                }
                {   // q2: unit tig+4, row r0
                    float ii = sigf(C[m][2][0] + bi1), ff = sigf(C[m][2][1] + bf1);
                    float gg = tanhf_(C[m][3][0] + bg1), oo = sigf(C[m][3][1] + bo1);
                    float c2 = fmaf(ff, cold.z, ii * gg);
                    float h2 = oo * tanhf_(c2);
                    cn.z = v0 ? c2 : cold.z;  hn.z = v0 ? h2 : hold.z;
                }
                {   // q3: unit tig+4, row r1
                    float ii = sigf(C[m][2][2] + bi1), ff = sigf(C[m][2][3] + bf1);
                    float gg = tanhf_(C[m][3][2] + bg1), oo = sigf(C[m][3][3] + bo1);
                    float c2 = fmaf(ff, cold.w, ii * gg);
                    float h2 = oo * tanhf_(c2);
                    cn.w = v1 ? c2 : cold.w;  hn.w = v1 ? h2 : hold.w;
                }
                cfr4[f4] = cn;
                hfr4[f4] = hn;
            }
        }
        __syncthreads();   // all mma reads + epilogue writes done before restaging
    }

    // ---- write final h (un-permute fragment order) ----
    for (int f = tid; f < 5120; f += NTHR) {
        float4 hv = hfr4[f];
        int nt = f / 1280, rem = f - nt * 1280;
        int m = rem >> 8, rem2 = rem & 255;
        int w2 = rem2 >> 5, lane2 = rem2 & 31;
        int g2 = lane2 >> 2, tg2 = lane2 & 3;
        int j0 = nt * 64 + w2 * 8 + tg2;
        int r0 = m * 16 + g2, r1 = r0 + 8;
        if (r0 < R) {
            out[(size_t)(n0 + r0) * DIM + j0]     = hv.x;
            out[(size_t)(n0 + r0) * DIM + j0 + 4] = hv.z;
        }
        if (r1 < R) {
            out[(size_t)(n0 + r1) * DIM + j0]     = hv.y;
            out[(size_t)(n0 + r1) * DIM + j0 + 4] = hv.w;
        }
    }
}

// ---------------- launch ----------------
extern "C" void kernel_launch(void* const* d_in, const int* in_sizes, int n_in,
                              void* d_out, int out_size) {
    const float* x       = (const float*)d_in[0];
    const int*   lengths = (const int*)d_in[1];
    const float* W_ih    = (const float*)d_in[2];
    const float* W_hh    = (const float*)d_in[3];
    const float* b_ih    = (const float*)d_in[4];
    const float* b_hh    = (const float*)d_in[5];
    float*       out     = (float*)d_out;
    (void)in_sizes; (void)n_in; (void)out_size;

    prep_kernel<<<512, 256>>>(W_ih, W_hh, b_ih, b_hh);

    const int smem = RP * PSTRIDE * 4;   // 166400 B
    (void)cudaFuncSetAttribute(lstm_fused_kernel,
                               cudaFuncAttributeMaxDynamicSharedMemorySize, smem);
    lstm_fused_kernel<<<GRID, NTHR, smem>>>(x, lengths, out);
}

// round 7
// speedup vs baseline: 5.3156x; 1.0036x over previous
#include <cuda_runtime.h>
#include <math.h>
#include <stdint.h>

#define NSEQ 10000
#define LSEQ 32
#define DIM  256
#define GDIM 1024
#define KDIM 512
#define GRID 148
#define NTHR 256
#define RP   80          // padded rows per CTA (5 x m16 tiles)
#define PSTRIDE 516      // stride mod 32 banks = 4 -> lane bank = g*4+tig, conflict-free

// ---------------- device scratch (no runtime allocation allowed) ----------------
__device__ float g_Wfrag[524288];        // fused [W_ih;W_hh] in exact B-fragment order, tf32-rounded
__device__ float g_bias[GDIM];           // b_ih + b_hh, original (gate,j) order
__device__ float g_hfrag[GRID * 20480];  // per-CTA h state, fragment order (float4/thread)
__device__ float g_cfrag[GRID * 20480];  // per-CTA c state, fragment order

// ---------------- helpers ----------------
__device__ __forceinline__ float sigf(float x) {
    return __fdividef(1.0f, 1.0f + __expf(-x));
}
__device__ __forceinline__ float tanhf_(float x) {
    return fmaf(2.0f, __fdividef(1.0f, 1.0f + __expf(-2.0f * x)), -1.0f);
}
__device__ __forceinline__ float tf32r(float x) {
    uint32_t u; asm("cvt.rna.tf32.f32 %0, %1;" : "=r"(u) : "f"(x));
    return __uint_as_float(u);
}
__device__ __forceinline__ void mma_tf32(float c[4],
                                         uint32_t a0, uint32_t a1, uint32_t a2, uint32_t a3,
                                         uint32_t b0, uint32_t b1) {
    asm volatile(
        "mma.sync.aligned.m16n8k8.row.col.f32.tf32.tf32.f32 "
        "{%0,%1,%2,%3},{%4,%5,%6,%7},{%8,%9},{%0,%1,%2,%3};"
        : "+f"(c[0]), "+f"(c[1]), "+f"(c[2]), "+f"(c[3])
        : "r"(a0), "r"(a1), "r"(a2), "r"(a3), "r"(b0), "r"(b1));
}

// ---------------- prep: build fragment-ordered fused weights + folded bias ----------------
// Gate-column permutation (position p in [0,1024)):
//   nt=p>>8, p8=p&255, w=p8>>5, c32=p8&31, s=c32>>3, c8=c32&7
//   unit u = (s>>1)*4 + (c8>>1); gate = (s&1)*2 + (c8&1)   (0=i,1=f,2=g,3=o)
//   hidden j = nt*64 + w*8 + u;  original W row = gate*256 + j
// B-fragment storage: g_Wfrag[((s8*64+ks)*32+lane)*2 + r] = Wfused[n=s8*8+(lane>>2)][k=ks*8+(lane&3)+4r]
__global__ void prep_kernel(const float* __restrict__ W_ih, const float* __restrict__ W_hh,
                            const float* __restrict__ b_ih, const float* __restrict__ b_hh) {
    int idx0 = blockIdx.x * blockDim.x + threadIdx.x;
    for (int idx = idx0; idx < 524288; idx += gridDim.x * blockDim.x) {
        int r    = idx & 1;
        int lane = (idx >> 1) & 31;
        int ks   = (idx >> 6) & 63;
        int s8   = idx >> 12;
        int n    = s8 * 8 + (lane >> 2);
        int k    = ks * 8 + (lane & 3) + 4 * r;
        int nt = n >> 8, p8 = n & 255;
        int w = p8 >> 5, c32 = p8 & 31, s = c32 >> 3, c8 = c32 & 7;
        int u    = ((s >> 1) << 2) + (c8 >> 1);
        int gate = ((s & 1) << 1) + (c8 & 1);
        int j    = nt * 64 + w * 8 + u;
        int row  = gate * 256 + j;
        float v  = (k < 256) ? W_ih[row * 256 + k] : W_hh[row * 256 + (k - 256)];
        g_Wfrag[idx] = tf32r(v);
    }
    if (idx0 < GDIM) g_bias[idx0] = b_ih[idx0] + b_hh[idx0];
}

// ---------------- fused persistent LSTM (tf32 tensor cores) ----------------
__global__ __launch_bounds__(NTHR, 1)
void lstm_fused_kernel(const float* __restrict__ x, const int* __restrict__ lengths,
                       float* __restrict__ out) {
    extern __shared__ float panel[];   // [RP][PSTRIDE]: cols 0..255 = x_t, 256..511 = h_t
    __shared__ float sbias[GDIM];
    __shared__ int   slen[RP];

    const int bid = blockIdx.x;
    const int n0  = (bid * NSEQ) / GRID;
    const int n1  = ((bid + 1) * NSEQ) / GRID;
    const int R   = n1 - n0;           // 67 or 68
    const int tid = threadIdx.x;
    const int w   = tid >> 5, lane = tid & 31, g = lane >> 2, tig = lane & 3;

    float*  hfr  = g_hfrag + bid * 20480;
    float*  cfr  = g_cfrag + bid * 20480;
    float4* hfr4 = (float4*)hfr;
    float4* cfr4 = (float4*)cfr;

    for (int i = tid; i < GDIM; i += NTHR) sbias[i] = g_bias[i];
    for (int i = tid; i < RP; i += NTHR)   slen[i] = (i < R) ? lengths[n0 + i] : 0;
    for (int i = tid; i < RP * PSTRIDE; i += NTHR) panel[i] = 0.0f;
    for (int i = tid; i < 20480; i += NTHR) { hfr[i] = 0.0f; cfr[i] = 0.0f; }
    __syncthreads();

    for (int t = 0; t < LSEQ; t++) {
        // ---- stage x_t (rows < R; pad rows stay zero) ----
        const float4* xg = (const float4*)(x + (size_t)n0 * LSEQ * DIM + (size_t)t * DIM);
        for (int i = tid; i < R * 64; i += NTHR) {
            int r = i >> 6, c = i & 63;
            float4 v = xg[(size_t)r * 2048 + c];   // row stride = LSEQ*DIM/4
            *(float4*)&panel[r * PSTRIDE + c * 4] = v;
        }
        // ---- stage h_t from fragment-ordered scratch ----
        for (int f = tid; f < 5120; f += NTHR) {
            float4 hv = hfr4[f];
            int nt = f / 1280, rem = f - nt * 1280;
            int m = rem >> 8, rem2 = rem & 255;
            int w2 = rem2 >> 5, lane2 = rem2 & 31;
            int g2 = lane2 >> 2, tg2 = lane2 & 3;
            int j0 = nt * 64 + w2 * 8 + tg2;
            int r0 = m * 16 + g2;
            panel[r0 * PSTRIDE + 256 + j0]           = hv.x;
            panel[(r0 + 8) * PSTRIDE + 256 + j0]     = hv.y;
            panel[r0 * PSTRIDE + 256 + j0 + 4]       = hv.z;
            panel[(r0 + 8) * PSTRIDE + 256 + j0 + 4] = hv.w;
        }
        __syncthreads();

        for (int nt = 0; nt < 4; nt++) {
            const int j = nt * 64 + w * 8 + tig;
            const float bi0 = sbias[j],       bf0 = sbias[256 + j];
            const float bg0 = sbias[512 + j], bo0 = sbias[768 + j];
            const float bi1 = sbias[j + 4],       bf1 = sbias[256 + j + 4];
            const float bg1 = sbias[512 + j + 4], bo1 = sbias[768 + j + 4];

            float C[5][4][4];
#pragma unroll
            for (int m = 0; m < 5; m++)
#pragma unroll
                for (int s = 0; s < 4; s++)
#pragma unroll
                    for (int q = 0; q < 4; q++) C[m][s][q] = 0.0f;

            const float2* bp[4];
#pragma unroll
            for (int s = 0; s < 4; s++) {
                int s8 = nt * 32 + w * 4 + s;
                bp[s] = (const float2*)g_Wfrag + (size_t)s8 * 2048 + lane;
            }
            float2 Bc[4];
#pragma unroll
            for (int s = 0; s < 4; s++) Bc[s] = bp[s][0];

            int rowb[5];
#pragma unroll
            for (int m = 0; m < 5; m++) rowb[m] = (m * 16 + g) * PSTRIDE;

#pragma unroll 2
            for (int ks = 0; ks < 64; ks++) {
                float2 Bn[4];
                int ks2 = (ks < 63) ? ks + 1 : 63;
#pragma unroll
                for (int s = 0; s < 4; s++) Bn[s] = bp[s][ks2 * 32];
                const int k = ks * 8 + tig;
#pragma unroll
                for (int m = 0; m < 5; m++) {
                    const float* ap = panel + rowb[m] + k;
                    uint32_t a0 = __float_as_uint(ap[0]);
                    uint32_t a2 = __float_as_uint(ap[4]);
                    uint32_t a1 = __float_as_uint(ap[8 * PSTRIDE]);
                    uint32_t a3 = __float_as_uint(ap[8 * PSTRIDE + 4]);
#pragma unroll
                    for (int s = 0; s < 4; s++)
                        mma_tf32(C[m][s], a0, a1, a2, a3,
                                 __float_as_uint(Bc[s].x), __float_as_uint(Bc[s].y));
                }
#pragma unroll
                for (int s = 0; s < 4; s++) Bc[s] = Bn[s];
            }

            // ---- register-local epilogue: thread holds i,f,g,o of its units ----
#pragma unroll
            for (int m = 0; m < 5; m++) {
                int f4 = ((nt * 5 + m) * 8 + w) * 32 + lane;
                float4 cold = cfr4[f4];
                float4 hold = hfr4[f4];
                int r0 = m * 16 + g, r1 = r0 + 8;
                bool v0 = t < slen[r0], v1 = t < slen[r1];
                float4 cn, hn;
                {   // q0: unit tig, row r0
                    float ii = sigf(C[m][0][0] + bi0), ff = sigf(C[m][0][1] + bf0);
                    float gg = tanhf_(C[m][1][0] + bg0), oo = sigf(C[m][1][1] + bo0);
                    float c2 = fmaf(ff, cold.x, ii * gg);
                    float h2 = oo * tanhf_(c2);
                    cn.x = v0 ? c2 : cold.x;  hn.x = v0 ? h2 : hold.x;
                }
                {   // q1: unit tig, row r1
                    float ii = sigf(C[m][0][2] + bi0), ff = sigf(C[m][0][3] + bf0);
                    float gg = tanhf_(C[m][1][2] + bg0), oo = sigf(C[m][1][3] + bo0);
                    float c2 = fmaf(ff, cold.y, ii * gg);
                    float h2 = oo * tanhf_(c2);
                    cn.y = v1 ? c2 : cold.y;  hn.y = v1 ? h2 : hold.y;
                }
                {   // q2: unit tig+4, row r0
                    float ii = sigf(C[m][2][0] + bi1), ff = sigf(C[m][2][1] + bf1);
                    float gg = tanhf_(C[m][3][0] + bg1), oo = sigf(C[m][3][1] + bo1);
                    float c2 = fmaf(ff, cold.z, ii * gg);
                    float h2 = oo * tanhf_(c2);
                    cn.z = v0 ? c2 : cold.z;  hn.z = v0 ? h2 : hold.z;
                }
                {   // q3: unit tig+4, row r1
                    float ii = sigf(C[m][2][2] + bi1), ff = sigf(C[m][2][3] + bf1);
                    float gg = tanhf_(C[m][3][2] + bg1), oo = sigf(C[m][3][3] + bo1);
                    float c2 = fmaf(ff, cold.w, ii * gg);
                    float h2 = oo * tanhf_(c2);
                    cn.w = v1 ? c2 : cold.w;  hn.w = v1 ? h2 : hold.w;
                }
                cfr4[f4] = cn;
                hfr4[f4] = hn;
            }
        }
        __syncthreads();   // all mma reads + epilogue writes done before restaging
    }

    // ---- write final h (un-permute fragment order) ----
    for (int f = tid; f < 5120; f += NTHR) {
        float4 hv = hfr4[f];
        int nt = f / 1280, rem = f - nt * 1280;
        int m = rem >> 8, rem2 = rem & 255;
        int w2 = rem2 >> 5, lane2 = rem2 & 31;
        int g2 = lane2 >> 2, tg2 = lane2 & 3;
        int j0 = nt * 64 + w2 * 8 + tg2;
        int r0 = m * 16 + g2, r1 = r0 + 8;
        if (r0 < R) {
            out[(size_t)(n0 + r0) * DIM + j0]     = hv.x;
            out[(size_t)(n0 + r0) * DIM + j0 + 4] = hv.z;
        }
        if (r1 < R) {
            out[(size_t)(n0 + r1) * DIM + j0]     = hv.y;
            out[(size_t)(n0 + r1) * DIM + j0 + 4] = hv.w;
        }
    }
}

// ---------------- launch ----------------
extern "C" void kernel_launch(void* const* d_in, const int* in_sizes, int n_in,
                              void* d_out, int out_size) {
    const float* x       = (const float*)d_in[0];
    const int*   lengths = (const int*)d_in[1];
    const float* W_ih    = (const float*)d_in[2];
    const float* W_hh    = (const float*)d_in[3];
    const float* b_ih    = (const float*)d_in[4];
    const float* b_hh    = (const float*)d_in[5];
    float*       out     = (float*)d_out;
    (void)in_sizes; (void)n_in; (void)out_size;

    prep_kernel<<<512, 256>>>(W_ih, W_hh, b_ih, b_hh);

    const int smem = RP * PSTRIDE * 4;   // 165120 B
    (void)cudaFuncSetAttribute(lstm_fused_kernel,
                               cudaFuncAttributeMaxDynamicSharedMemorySize, smem);
    lstm_fused_kernel<<<GRID, NTHR, smem>>>(x, lengths, out);
}